// round 5
// baseline (speedup 1.0000x reference)
#include <cuda_runtime.h>
#include <cstdint>
#include <math.h>

// ---------------- problem constants ----------------
#define HW      16384           // 128*128 spatial
#define CH      256
#define KTOT    2304            // 256*9
#define NANCH   147456          // HW*9
#define TOPK    6000
#define POSTK   300
#define STRIDE  8.0f
#define IMSZ    1024.0f
#define DWCLIP  4.135166556742356f
#define NMSTHR  0.7f
#define MINSZ   16.0f

#define PLW     132
#define PLH     130
#define PLANE   (PLW*PLH)       // 17160
#define NPAD    (CH*PLANE)      // 4392960

#define NSEL    8192
#define NBITW   188             // ceil(6016/32)

// ---------------- scratch (device globals; no allocations allowed) ----------------
__device__ float g_rpnfeat[CH * HW];                 // conv output [oc][p]
__device__ float g_featpad[NPAD];                    // padded input
__device__ float g_wt[KTOT * CH];                    // transposed weights [k][oc]
__device__ float g_boxes[NANCH * 4];                 // decoded boxes
__device__ unsigned long long g_keys[NANCH];         // (scorebits<<32)|~idx
__device__ unsigned long long g_sel[NSEL];           // selected candidates
__device__ int g_hist1[4096];
__device__ int g_hist2[4096];
__device__ int g_B1;
__device__ int g_cntgt;
__device__ unsigned g_T;
__device__ int g_selcnt;

// ---------------- f32x2 helper ----------------
__device__ __forceinline__ void ffma2(unsigned long long& d, unsigned long long a, unsigned long long b) {
    asm("fma.rn.f32x2 %0, %1, %2, %0;" : "+l"(d) : "l"(a), "l"(b));
}

// =====================================================================
// prep: pad feature map into [256][130][132] with zero halo
// =====================================================================
__global__ __launch_bounds__(1024)
void prep_pad(const float* __restrict__ feat)
{
    int idx = blockIdx.x * 1024 + threadIdx.x;
    if (idx >= NPAD) return;
    int ic  = idx / PLANE;
    int rem = idx - ic * PLANE;
    int yy  = rem / PLW;
    int xx  = rem - yy * PLW;
    float v = 0.f;
    if (yy >= 1 && yy <= 128 && xx >= 1 && xx <= 128)
        v = feat[ic * HW + ((yy - 1) << 7) + (xx - 1)];
    g_featpad[idx] = v;
}

// prep: transpose weights w[oc][k] -> g_wt[k][oc]; zero histograms
__global__ __launch_bounds__(1024)
void prep_misc(const float* __restrict__ w)
{
    int idx = blockIdx.x * 1024 + threadIdx.x;   // 576 blocks
    if (idx < 4096) g_hist1[idx] = 0;
    else if (idx < 8192) g_hist2[idx - 4096] = 0;
    int k = idx >> 8, oc = idx & 255;
    g_wt[idx] = w[oc * KTOT + k];
}

// =====================================================================
// conv 3x3 256->256 + bias + ReLU, packed FFMA2, spill-proof.
// Block: image row y (128 px) x 128 oc. 256 thr, per-thread 8oc x 8px
// as 4 oc-pairs x 8 px f32x2 accs. BK=16, register double buffering.
// B tile stored DUPLICATED (f32x2 pairs) with 18-float lane skew so
// each B operand is one conflict-free LDS.64 (no per-kk MOV dup).
// =====================================================================
__global__ __launch_bounds__(256, 2)
void conv3x3_relu(const float* __restrict__ bias)
{
    __shared__ float As[16][132];        // [kk][oc] (pad 4)
    __shared__ float Bsd[16][288];       // [kk][dup px pairs, skewed]
    __shared__ int soff[KTOT];

    const int tid = threadIdx.x;
    const int tx = tid & 15;
    const int ty = tid >> 4;
    const int y = blockIdx.x;            // image row
    const int oc0 = blockIdx.y << 7;

    for (int k = tid; k < KTOT; k += 256) {
        int ic = k / 9, r = k - ic * 9, ky = r / 3, kx = r - ky * 3;
        soff[k] = ic * PLANE + ky * PLW + kx;
    }

    unsigned long long acc[4][8];
#pragma unroll
    for (int i = 0; i < 4; i++)
#pragma unroll
        for (int n = 0; n < 8; n++) acc[i][n] = 0ull;

    const int kkS  = tid >> 4;           // stage row this thread fills (0..15)
    const int cS   = (tid & 15) * 8;     // col chunk (A: oc, B: px)
    const int bcol = 2 * cS + 2 * (tid & 15);   // dup-skew col = 18*(tid&15)
    const int ybase = y * PLW;

    __syncthreads();                     // soff ready

    float rA[8], rB[8];
    // prefetch kb = 0
    {
        const float* wp = &g_wt[kkS * CH + oc0 + cS];
        *(float4*)&rA[0] = *(const float4*)&wp[0];
        *(float4*)&rA[4] = *(const float4*)&wp[4];
        const float* gp = g_featpad + soff[kkS] + ybase + cS;
#pragma unroll
        for (int j = 0; j < 8; j++) rB[j] = gp[j];
    }

    for (int kb = 0; kb < KTOT; kb += 16) {
        // store stage to smem
        *(float4*)&As[kkS][cS]     = *(float4*)&rA[0];
        *(float4*)&As[kkS][cS + 4] = *(float4*)&rA[4];
        {
            float2* bp = (float2*)&Bsd[kkS][bcol];
#pragma unroll
            for (int j = 0; j < 8; j++) bp[j] = make_float2(rB[j], rB[j]);
        }
        __syncthreads();

        // prefetch next stage (overlaps with compute below)
        if (kb + 16 < KTOT) {
            const float* wp = &g_wt[(kb + 16 + kkS) * CH + oc0 + cS];
            *(float4*)&rA[0] = *(const float4*)&wp[0];
            *(float4*)&rA[4] = *(const float4*)&wp[4];
            const float* gp = g_featpad + soff[kb + 16 + kkS] + ybase + cS;
#pragma unroll
            for (int j = 0; j < 8; j++) rB[j] = gp[j];
        }

        // compute 16 k-steps
#pragma unroll
        for (int kk = 0; kk < 16; kk++) {
            const unsigned long long* A64 = (const unsigned long long*)&As[kk][0];
            const unsigned long long* B64 = (const unsigned long long*)&Bsd[kk][0] + 9 * tx;
            unsigned long long a0 = A64[ty];
            unsigned long long a1 = A64[16 + ty];
            unsigned long long a2 = A64[32 + ty];
            unsigned long long a3 = A64[48 + ty];
#pragma unroll
            for (int n = 0; n < 8; n++) {
                unsigned long long bd = B64[n];
                ffma2(acc[0][n], a0, bd);
                ffma2(acc[1][n], a1, bd);
                ffma2(acc[2][n], a2, bd);
                ffma2(acc[3][n], a3, bd);
            }
        }
        __syncthreads();
    }

#pragma unroll
    for (int i = 0; i < 4; i++) {
        int oc = oc0 + 32 * i + 2 * ty;
        float b0 = bias[oc], b1 = bias[oc + 1];
        float lo[8], hi[8];
#pragma unroll
        for (int n = 0; n < 8; n++) {
            lo[n] = fmaxf(__uint_as_float((unsigned)(acc[i][n] & 0xFFFFFFFFull)) + b0, 0.f);
            hi[n] = fmaxf(__uint_as_float((unsigned)(acc[i][n] >> 32)) + b1, 0.f);
        }
        int p0 = oc * HW + (y << 7) + tx * 8;
        *(float4*)&g_rpnfeat[p0]          = make_float4(lo[0], lo[1], lo[2], lo[3]);
        *(float4*)&g_rpnfeat[p0 + 4]      = make_float4(lo[4], lo[5], lo[6], lo[7]);
        *(float4*)&g_rpnfeat[p0 + HW]     = make_float4(hi[0], hi[1], hi[2], hi[3]);
        *(float4*)&g_rpnfeat[p0 + HW + 4] = make_float4(hi[4], hi[5], hi[6], hi[7]);
    }
}

// =====================================================================
// 1x1 heads + decode, 4-way channel split for parallelism.
// Block: 64 px, 256 thr (q = tid>>6 handles channels [64q,64q+64)).
// dyn smem: ws[45][256] | red[3][64][46] | sums[64][46]
// =====================================================================
#define HSM_WS    (45*256)
#define HSM_RED   (3*64*46)
#define HSM_SUMS  (64*46)
#define HSM_BYTES ((HSM_WS + HSM_RED + HSM_SUMS) * 4)

__global__ __launch_bounds__(256)
void heads_decode(const float* __restrict__ cls_w, const float* __restrict__ cls_b,
                  const float* __restrict__ bbox_w, const float* __restrict__ bbox_b)
{
    extern __shared__ float hsm[];
    float* ws   = hsm;                       // ws[j*256+c]
    float* red  = hsm + HSM_WS;              // red[((q-1)*64+pl)*46 + j]
    float* sums = red + HSM_RED;             // sums[pl*46 + j]

    const int tid = threadIdx.x;
    for (int i = tid; i < 9 * 256; i += 256)  ws[(i >> 8) * 256 + (i & 255)] = cls_w[i];
    for (int i = tid; i < 36 * 256; i += 256) ws[(9 + (i >> 8)) * 256 + (i & 255)] = bbox_w[i];
    __syncthreads();

    const int q  = tid >> 6;
    const int pl = tid & 63;
    const int p  = (blockIdx.x << 6) + pl;

    float acc[45];
#pragma unroll
    for (int j = 0; j < 45; j++) acc[j] = 0.f;

    const float* rf = g_rpnfeat + (q << 6) * HW + p;
    const float* wq = ws + (q << 6);
    for (int cc = 0; cc < 64; cc++) {
        float v = rf[cc * HW];
#pragma unroll
        for (int j = 0; j < 45; j++) acc[j] = fmaf(wq[j * 256 + cc], v, acc[j]);
    }

    if (q) {
        float* r = red + ((q - 1) * 64 + pl) * 46;
#pragma unroll
        for (int j = 0; j < 45; j++) r[j] = acc[j];
    }
    __syncthreads();
    if (q == 0) {
        float* s = sums + pl * 46;
#pragma unroll
        for (int j = 0; j < 45; j++) {
            float t = acc[j];
            t += red[(pl) * 46 + j];
            t += red[(64 + pl) * 46 + j];
            t += red[(128 + pl) * 46 + j];
            s[j] = t;
        }
    }
    __syncthreads();

    const float AR[3]  = {0.5f, 1.0f, 2.0f};
    const float SCL[3] = {128.f, 256.f, 512.f};

    for (int t = tid; t < 576; t += 256) {
        int pxl = t / 9;
        int a   = t - pxl * 9;
        const float* s = sums + pxl * 46;
        int pg = (blockIdx.x << 6) + pxl;
        int x = pg & 127;
        int yv = pg >> 7;
        float sx = (float)x * STRIDE;
        float sy = (float)yv * STRIDE;

        int ia = a / 3, is_ = a - ia * 3;
        float hr  = sqrtf(AR[ia]);
        float wr  = __fdiv_rn(1.0f, hr);
        float hsv = __fmul_rn(hr, SCL[is_]);
        float wsv = __fmul_rn(wr, SCL[is_]);
        float bx1 = rintf(__fmul_rn(-wsv, 0.5f));
        float by1 = rintf(__fmul_rn(-hsv, 0.5f));
        float bx2 = rintf(__fmul_rn(wsv, 0.5f));
        float by2 = rintf(__fmul_rn(hsv, 0.5f));
        float ax1 = __fadd_rn(sx, bx1), ay1 = __fadd_rn(sy, by1);
        float ax2 = __fadd_rn(sx, bx2), ay2 = __fadd_rn(sy, by2);
        float aw = __fsub_rn(ax2, ax1), ah = __fsub_rn(ay2, ay1);
        float cx = __fadd_rn(ax1, __fmul_rn(0.5f, aw));
        float cy = __fadd_rn(ay1, __fmul_rn(0.5f, ah));

        float dx = s[9 + a * 4 + 0] + bbox_b[a * 4 + 0];
        float dy = s[9 + a * 4 + 1] + bbox_b[a * 4 + 1];
        float dw = fminf(s[9 + a * 4 + 2] + bbox_b[a * 4 + 2], DWCLIP);
        float dh = fminf(s[9 + a * 4 + 3] + bbox_b[a * 4 + 3], DWCLIP);

        float px = __fadd_rn(__fmul_rn(dx, aw), cx);
        float py = __fadd_rn(__fmul_rn(dy, ah), cy);
        float pw = __fmul_rn((float)exp((double)dw), aw);
        float ph = __fmul_rn((float)exp((double)dh), ah);

        float x1 = __fsub_rn(px, __fmul_rn(0.5f, pw));
        float y1 = __fsub_rn(py, __fmul_rn(0.5f, ph));
        float x2 = __fadd_rn(px, __fmul_rn(0.5f, pw));
        float y2 = __fadd_rn(py, __fmul_rn(0.5f, ph));

        int idx = pg * 9 + a;
        g_boxes[idx * 4 + 0] = x1;
        g_boxes[idx * 4 + 1] = y1;
        g_boxes[idx * 4 + 2] = x2;
        g_boxes[idx * 4 + 3] = y2;

        float cls = s[a] + cls_b[a];
        float sc = (float)(1.0 / (1.0 + exp(-(double)cls)));
        unsigned sb = __float_as_uint(sc);
        g_keys[idx] = ((unsigned long long)sb << 32) | (unsigned)(0xFFFFFFFFu - (unsigned)idx);
    }
}

// =====================================================================
// Two-level radix select (unchanged from R3)
// =====================================================================
__global__ __launch_bounds__(1024)
void hist_top()
{
    __shared__ int h[4096];
    const int tid = threadIdx.x;
    for (int i = tid; i < 4096; i += 1024) h[i] = 0;
    __syncthreads();
    for (int i = blockIdx.x * 1024 + tid; i < NANCH; i += gridDim.x * 1024)
        atomicAdd(&h[(unsigned)(g_keys[i] >> 52)], 1);
    __syncthreads();
    for (int i = tid; i < 4096; i += 1024) {
        int v = h[i];
        if (v) atomicAdd(&g_hist1[i], v);
    }
}

__global__ __launch_bounds__(1024)
void hist_in_bin()
{
    __shared__ int h[4096];
    const int tid = threadIdx.x;
    const unsigned b1 = (unsigned)g_B1;
    for (int i = tid; i < 4096; i += 1024) h[i] = 0;
    __syncthreads();
    for (int i = blockIdx.x * 1024 + tid; i < NANCH; i += gridDim.x * 1024) {
        unsigned long long key = g_keys[i];
        if ((unsigned)(key >> 52) == b1)
            atomicAdd(&h[(unsigned)((key >> 40) & 0xFFFull)], 1);
    }
    __syncthreads();
    for (int i = tid; i < 4096; i += 1024) {
        int v = h[i];
        if (v) atomicAdd(&g_hist2[i], v);
    }
}

__global__ __launch_bounds__(1024)
void scan_select(int phase)
{
    __shared__ int s[1024];
    const int t = threadIdx.x;
    const int* h = phase ? g_hist2 : g_hist1;
    const int base = phase ? g_cntgt : 0;
    int c[4];
    c[0] = h[4 * t]; c[1] = h[4 * t + 1]; c[2] = h[4 * t + 2]; c[3] = h[4 * t + 3];
    int v = c[0] + c[1] + c[2] + c[3];
    s[t] = v;
    __syncthreads();
    for (int off = 1; off < 1024; off <<= 1) {
        int add = (t + off < 1024) ? s[t + off] : 0;
        __syncthreads();
        v += add;
        s[t] = v;
        __syncthreads();
    }
    int suff = s[t];
    int above = (t < 1023) ? s[t + 1] : 0;
    if (base + above < TOPK && base + suff >= TOPK) {
        int cum = base + above;
#pragma unroll
        for (int b = 3; b >= 0; b--) {
            int hb = c[b];
            if (cum + hb >= TOPK) {
                if (phase == 0) { g_B1 = 4 * t + b; g_cntgt = cum; }
                else            { g_T = ((unsigned)g_B1 << 12) | (unsigned)(4 * t + b); }
                break;
            }
            cum += hb;
        }
    }
    if (phase) {
        if (t == 0) g_selcnt = 0;
        for (int i = t; i < NSEL; i += 1024) g_sel[i] = 0ull;
    }
}

__global__ __launch_bounds__(1024)
void compact_sel()
{
    const unsigned T = g_T;
    for (int i = blockIdx.x * 1024 + threadIdx.x; i < NANCH; i += gridDim.x * 1024) {
        unsigned long long key = g_keys[i];
        if ((unsigned)(key >> 40) >= T) {
            int p = atomicAdd(&g_selcnt, 1);
            if (p < NSEL) g_sel[p] = key;
        }
    }
}

// =====================================================================
// Sort the <=8192 candidates descending: 4x local bitonic + 1-block merge.
// =====================================================================
__global__ __launch_bounds__(1024)
void sel_local()
{
    __shared__ unsigned long long s[2048];
    const int base = blockIdx.x << 11;
    s[threadIdx.x]        = g_sel[base + threadIdx.x];
    s[threadIdx.x + 1024] = g_sel[base + threadIdx.x + 1024];
    __syncthreads();
    for (int k = 2; k <= 2048; k <<= 1) {
        for (int j = k >> 1; j > 0; j >>= 1) {
            int t = threadIdx.x;
            int i = (t << 1) - (t & (j - 1));
            bool desc = (((base + i) & k) == 0);
            unsigned long long a = s[i], b = s[i + j];
            if ((a < b) == desc) { s[i] = b; s[i + j] = a; }
            __syncthreads();
        }
    }
    g_sel[base + threadIdx.x]        = s[threadIdx.x];
    g_sel[base + threadIdx.x + 1024] = s[threadIdx.x + 1024];
}

__global__ __launch_bounds__(1024)
void sel_merge()
{
    extern __shared__ unsigned long long s[];
    const int tid = threadIdx.x;
#pragma unroll
    for (int q = 0; q < 8; q++) s[tid + (q << 10)] = g_sel[tid + (q << 10)];
    __syncthreads();
    for (int k = 4096; k <= NSEL; k <<= 1) {
        for (int j = k >> 1; j > 0; j >>= 1) {
#pragma unroll
            for (int q = 0; q < 4; q++) {
                int t = tid + (q << 10);
                int i = (t << 1) - (t & (j - 1));
                bool desc = ((i & k) == 0);
                unsigned long long a = s[i], b = s[i + j];
                if ((a < b) == desc) { s[i] = b; s[i + j] = a; }
            }
            __syncthreads();
        }
    }
#pragma unroll
    for (int q = 0; q < 8; q++) g_sel[tid + (q << 10)] = s[tid + (q << 10)];
}

// =====================================================================
// clip + min-size + greedy NMS with removed-bitmap + register boxes.
// Fixed ownership: thread owns j = tid + 1024k (k<6). Early exit @300.
// dyn smem: sx1..sar 5*6000 floats + bitmap 188 u32
// =====================================================================
__global__ __launch_bounds__(1024)
void nms_out(float* __restrict__ out)
{
    extern __shared__ float sm[];
    float* sx1 = sm;
    float* sy1 = sm + TOPK;
    float* sx2 = sm + 2 * TOPK;
    float* sy2 = sm + 3 * TOPK;
    float* sar = sm + 4 * TOPK;
    unsigned* sbits = (unsigned*)(sm + 5 * TOPK);
    __shared__ int keepList[POSTK];

    const int tid = threadIdx.x;
    if (tid < NBITW) sbits[tid] = 0u;
    __syncthreads();

    float rx1[6], ry1[6], rx2[6], ry2[6], rar[6];
    unsigned remloc = 0;
#pragma unroll
    for (int k = 0; k < 6; k++) {
        int j = tid + (k << 10);
        if (j < TOPK) {
            unsigned long long key = g_sel[j];
            unsigned idx = 0xFFFFFFFFu - (unsigned)(key & 0xFFFFFFFFull);
            float b0 = g_boxes[idx * 4 + 0];
            float b1 = g_boxes[idx * 4 + 1];
            float b2 = g_boxes[idx * 4 + 2];
            float b3 = g_boxes[idx * 4 + 3];
            float x1 = fminf(fmaxf(b0, 0.f), IMSZ);
            float y1 = fminf(fmaxf(b1, 0.f), IMSZ);
            float x2 = fminf(fmaxf(b2, 0.f), IMSZ);
            float y2 = fminf(fmaxf(b3, 0.f), IMSZ);
            float wv = __fsub_rn(x2, x1);
            float hv = __fsub_rn(y2, y1);
            sx1[j] = x1; sy1[j] = y1; sx2[j] = x2; sy2[j] = y2;
            float ar = __fmul_rn(wv, hv);
            sar[j] = ar;
            rx1[k] = x1; ry1[k] = y1; rx2[k] = x2; ry2[k] = y2; rar[k] = ar;
            if (!(wv >= MINSZ && hv >= MINSZ)) {
                remloc |= 1u << k;
                atomicOr(&sbits[j >> 5], 1u << (j & 31));
            }
        } else {
            remloc |= 1u << k;
        }
    }
    if (tid == 0) atomicOr(&sbits[NBITW - 1], 0xFFFF0000u);  // bits 6000..6015
    __syncthreads();

    int count = 0;
    int i = 0;
    for (;;) {
        // find next kept i (identical scan in all threads)
        while (i < TOPK) {
            unsigned w = (~sbits[i >> 5]) & (0xFFFFFFFFu << (i & 31));
            if (w) { i = (i & ~31) + (__ffs(w) - 1); break; }
            i = (i & ~31) + 32;
        }
        if (i >= TOPK) break;
        if (tid == 0) keepList[count] = i;
        float bx1 = sx1[i], by1 = sy1[i], bx2 = sx2[i], by2 = sy2[i], ba = sar[i];
#pragma unroll
        for (int k = 0; k < 6; k++) {
            int j = tid + (k << 10);
            if (j > i && !((remloc >> k) & 1u)) {
                float xx1 = fmaxf(bx1, rx1[k]);
                float yy1 = fmaxf(by1, ry1[k]);
                float xx2 = fminf(bx2, rx2[k]);
                float yy2 = fminf(by2, ry2[k]);
                float iw = fmaxf(__fsub_rn(xx2, xx1), 0.f);
                float ih = fmaxf(__fsub_rn(yy2, yy1), 0.f);
                float inter = __fmul_rn(iw, ih);
                float denom = __fsub_rn(__fadd_rn(ba, rar[k]), inter);
                if (__fdiv_rn(inter, denom) > NMSTHR) {
                    remloc |= 1u << k;
                    atomicOr(&sbits[j >> 5], 1u << (j & 31));
                }
            }
        }
        count++;
        i++;
        if (count >= POSTK) break;
        __syncthreads();
    }
    __syncthreads();

    for (int t = tid; t < POSTK; t += blockDim.x) {
        if (t < count) {
            int ii = keepList[t];
            unsigned long long key = g_sel[ii];
            out[t * 5 + 0] = sx1[ii];
            out[t * 5 + 1] = sy1[ii];
            out[t * 5 + 2] = sx2[ii];
            out[t * 5 + 3] = sy2[ii];
            out[t * 5 + 4] = __uint_as_float((unsigned)(key >> 32));
        } else {
            out[t * 5 + 0] = 0.f; out[t * 5 + 1] = 0.f; out[t * 5 + 2] = 0.f;
            out[t * 5 + 3] = 0.f; out[t * 5 + 4] = 0.f;
        }
    }
}

// ---------------- launch ----------------
extern "C" void kernel_launch(void* const* d_in, const int* in_sizes, int n_in,
                              void* d_out, int out_size)
{
    (void)in_sizes; (void)n_in; (void)out_size;
    const float* feat   = (const float*)d_in[1];
    const float* conv_w = (const float*)d_in[2];
    const float* conv_b = (const float*)d_in[3];
    const float* cls_w  = (const float*)d_in[4];
    const float* cls_b  = (const float*)d_in[5];
    const float* bbox_w = (const float*)d_in[6];
    const float* bbox_b = (const float*)d_in[7];
    float* out = (float*)d_out;

    prep_pad<<<(NPAD + 1023) / 1024, 1024>>>(feat);
    prep_misc<<<(KTOT * CH) / 1024, 1024>>>(conv_w);
    conv3x3_relu<<<dim3(128, 2), 256>>>(conv_b);

    cudaFuncSetAttribute(heads_decode, cudaFuncAttributeMaxDynamicSharedMemorySize, HSM_BYTES);
    heads_decode<<<256, 256, HSM_BYTES>>>(cls_w, cls_b, bbox_w, bbox_b);

    hist_top<<<144, 1024>>>();
    scan_select<<<1, 1024>>>(0);
    hist_in_bin<<<144, 1024>>>();
    scan_select<<<1, 1024>>>(1);
    compact_sel<<<144, 1024>>>();
    sel_local<<<4, 1024>>>();
    cudaFuncSetAttribute(sel_merge, cudaFuncAttributeMaxDynamicSharedMemorySize, NSEL * 8);
    sel_merge<<<1, 1024, NSEL * 8>>>();

    const int nms_smem = TOPK * 5 * (int)sizeof(float) + NBITW * (int)sizeof(unsigned);
    cudaFuncSetAttribute(nms_out, cudaFuncAttributeMaxDynamicSharedMemorySize, nms_smem);
    nms_out<<<1, 1024, nms_smem>>>(out);
}

// round 7
// speedup vs baseline: 1.0928x; 1.0928x over previous
#include <cuda_runtime.h>
#include <cuda_bf16.h>
#include <cstdint>
#include <math.h>

// ---------------- problem constants ----------------
#define HW      16384           // 128*128 spatial
#define CH      256
#define NANCH   147456          // HW*9
#define TOPK    6000
#define POSTK   300
#define STRIDE  8.0f
#define IMSZ    1024.0f
#define DWCLIP  4.135166556742356f
#define NMSTHR  0.7f
#define MINSZ   16.0f

#define PADW    132
#define PADH    130
#define PADHW   (PADW*PADH)     // 17160

#define NSEL    8192
#define NBITW   188             // ceil(6016/32)

// conv tiling: CTA = 128 oc x 256 px, BK=32 ic, 72 stages (9 taps x 8 chunks)
#define NSTAGE  72
#define RSB     80              // smem row stride bytes (32 bf16 data + pad)
#define RSW     20              // row stride in words
#define A_SEC   10240           // 128 rows * 80B
#define B_SEC   20480           // 256 rows * 80B
#define BUFB    (3*A_SEC + 3*B_SEC)   // 92160 B per stage buffer
#define DYNSM   (2*BUFB)              // 184320

// ---------------- scratch (device globals; no allocations allowed) ----------------
__device__ float g_rpnfeat[CH * HW];                                  // conv out [oc][p]
__device__ __align__(256) __nv_bfloat16 g_tb[3 * PADHW * 256];        // feat splits [s][y][x][ic]
__device__ __align__(256) __nv_bfloat16 g_wa[3 * 9 * 256 * 256];      // w splits [s][tap][oc][ic]
__device__ float g_boxes[NANCH * 4];
__device__ unsigned long long g_keys[NANCH];
__device__ unsigned long long g_sel[NSEL];
__device__ int g_hist1[4096];
__device__ int g_hist2[4096];
__device__ int g_B1;
__device__ int g_cntgt;
__device__ unsigned g_T;
__device__ int g_selcnt;

// ---------------- helpers ----------------
__device__ __forceinline__ uint32_t smem_u32(const void* p) {
    uint32_t a;
    asm("{ .reg .u64 t; cvta.to.shared.u64 t, %1; cvt.u32.u64 %0, t; }" : "=r"(a) : "l"(p));
    return a;
}
#define CP_ASYNC16(dst, src) \
    asm volatile("cp.async.cg.shared.global [%0], [%1], 16;" :: "r"(dst), "l"(src))
#define CP_COMMIT()  asm volatile("cp.async.commit_group;" ::: "memory")
#define CP_WAIT0()   asm volatile("cp.async.wait_group 0;" ::: "memory")

#define MMA16816(d, a, b) \
    asm volatile("mma.sync.aligned.m16n8k16.row.col.f32.bf16.bf16.f32 " \
        "{%0,%1,%2,%3}, {%4,%5,%6,%7}, {%8,%9}, {%0,%1,%2,%3};" \
        : "+f"((d)[0]), "+f"((d)[1]), "+f"((d)[2]), "+f"((d)[3]) \
        : "r"((a)[0]), "r"((a)[1]), "r"((a)[2]), "r"((a)[3]), "r"((b)[0]), "r"((b)[1]))

// =====================================================================
// prep: split weights into 3 bf16 planes [split][tap][oc][ic]; zero hists
// =====================================================================
__global__ __launch_bounds__(256)
void prep_w(const float* __restrict__ w)
{
    int idx = blockIdx.x * 256 + threadIdx.x;     // 65536: oc*256+ic
    if (idx < 4096) g_hist1[idx] = 0;
    else if (idx < 8192) g_hist2[idx - 4096] = 0;
    int oc = idx >> 8, ic = idx & 255;
#pragma unroll
    for (int tap = 0; tap < 9; tap++) {
        float x = w[oc * 2304 + ic * 9 + tap];
        __nv_bfloat16 b0 = __float2bfloat16(x);
        float r1 = x - __bfloat162float(b0);
        __nv_bfloat16 b1 = __float2bfloat16(r1);
        __nv_bfloat16 b2 = __float2bfloat16(r1 - __bfloat162float(b1));
        int base = (tap * 256 + oc) * 256 + ic;
        g_wa[base] = b0;
        g_wa[9 * 65536 + base] = b1;
        g_wa[18 * 65536 + base] = b2;
    }
}

// prep: transpose + pad feat -> [split][y'][x'][ic] bf16 (halo zero)
__global__ __launch_bounds__(256)
void prep_feat(const float* __restrict__ feat)
{
    int yp = blockIdx.x;          // 0..129
    int ic = threadIdx.x;         // 0..255
    for (int xp = 0; xp < PADW; xp++) {
        float v = 0.f;
        if (yp >= 1 && yp <= 128 && xp >= 1 && xp <= 128)
            v = feat[ic * HW + ((yp - 1) << 7) + (xp - 1)];
        __nv_bfloat16 b0 = __float2bfloat16(v);
        float r1 = v - __bfloat162float(b0);
        __nv_bfloat16 b1 = __float2bfloat16(r1);
        __nv_bfloat16 b2 = __float2bfloat16(r1 - __bfloat162float(b1));
        int base = (yp * PADW + xp) * 256 + ic;
        g_tb[base] = b0;
        g_tb[PADHW * 256 + base] = b1;
        g_tb[2 * PADHW * 256 + base] = b2;
    }
}

// =====================================================================
// conv 3x3 256->256 + bias + ReLU via mma.sync bf16 3-split (6 products)
// =====================================================================
__device__ __forceinline__ void issue_stage(uint32_t sbase, int s, int tid, int yblk, int oc0)
{
    const int tap = s >> 3;
    const int icb = (s & 7) << 6;        // ic0 * 2 bytes
    const int ky = tap / 3, kx = tap - ky * 3;
#pragma unroll
    for (int i = 0; i < 3; i++) {
        int rid = tid + (i << 9);
        if (rid < 1152) {
            const char* src;
            uint32_t dst;
            if (rid < 384) {
                int sp = rid >> 7, r = rid & 127;
                src = (const char*)g_wa + ((sp * 9 + tap) * 256 + oc0 + r) * 512 + icb;
                dst = sbase + sp * A_SEC + r * RSB;
            } else {
                int rid2 = rid - 384;
                int sp = rid2 >> 8, p = rid2 & 255;
                int yy = (yblk << 1) + (p >> 7) + ky;
                int xx = (p & 127) + kx;
                src = (const char*)g_tb + (sp * PADHW + yy * PADW + xx) * 512 + icb;
                dst = sbase + 3 * A_SEC + sp * B_SEC + p * RSB;
            }
#pragma unroll
            for (int c = 0; c < 4; c++)
                CP_ASYNC16(dst + c * 16, src + c * 16);
        }
    }
    CP_COMMIT();
}

__global__ void __launch_bounds__(512, 1) conv_mma(const float* __restrict__ bias)
{
    extern __shared__ char dsm[];
    const uint32_t smem_base = smem_u32(dsm);
    const int tid = threadIdx.x;
    const int yblk = blockIdx.x;          // 0..63 (pair of image rows)
    const int oc0 = blockIdx.y << 7;
    const int wid = tid >> 5, lane = tid & 31;
    const int wm = wid & 3, wn = wid >> 2;
    const int g = lane >> 2, t = lane & 3;

    float acc[2][8][4];
#pragma unroll
    for (int mt = 0; mt < 2; mt++)
#pragma unroll
        for (int nt = 0; nt < 8; nt++)
#pragma unroll
            for (int c = 0; c < 4; c++) acc[mt][nt][c] = 0.f;

    issue_stage(smem_base, 0, tid, yblk, oc0);
    CP_WAIT0();
    __syncthreads();

    for (int s = 0; s < NSTAGE; s++) {
        if (s + 1 < NSTAGE)
            issue_stage(smem_base + ((s + 1) & 1) * BUFB, s + 1, tid, yblk, oc0);

        const uint32_t* smw = (const uint32_t*)(dsm + (s & 1) * BUFB);
#pragma unroll
        for (int k16 = 0; k16 < 2; k16++) {
            const int ko = k16 * 8 + t;
            uint32_t af[3][2][4];
#pragma unroll
            for (int sp = 0; sp < 3; sp++)
#pragma unroll
                for (int mt = 0; mt < 2; mt++) {
                    int row = wm * 32 + mt * 16 + g;
                    int base = sp * (A_SEC / 4) + row * RSW + ko;
                    af[sp][mt][0] = smw[base];
                    af[sp][mt][1] = smw[base + 8 * RSW];
                    af[sp][mt][2] = smw[base + 4];
                    af[sp][mt][3] = smw[base + 8 * RSW + 4];
                }
#pragma unroll
            for (int sb = 0; sb < 3; sb++) {
                uint32_t bf_[8][2];
#pragma unroll
                for (int nt = 0; nt < 8; nt++) {
                    int n = wn * 64 + nt * 8 + g;
                    int base = 3 * (A_SEC / 4) + sb * (B_SEC / 4) + n * RSW + ko;
                    bf_[nt][0] = smw[base];
                    bf_[nt][1] = smw[base + 4];
                }
                const int nsa = (sb == 0) ? 3 : ((sb == 1) ? 2 : 1);
#pragma unroll
                for (int sa = 0; sa < 3; sa++) {
                    if (sa < nsa) {
#pragma unroll
                        for (int mt = 0; mt < 2; mt++)
#pragma unroll
                            for (int nt = 0; nt < 8; nt++)
                                MMA16816(acc[mt][nt], af[sa][mt], bf_[nt]);
                    }
                }
            }
        }

        if (s + 1 < NSTAGE) {
            CP_WAIT0();
            __syncthreads();
        }
    }

    // epilogue: bias + relu, direct STG (float2)
#pragma unroll
    for (int mt = 0; mt < 2; mt++) {
        int ocl = oc0 + wm * 32 + mt * 16 + g;
        float b0 = bias[ocl];
        float b1 = bias[ocl + 8];
#pragma unroll
        for (int nt = 0; nt < 8; nt++) {
            int col = wn * 64 + nt * 8 + 2 * t;
            float2 lo, hi;
            lo.x = fmaxf(acc[mt][nt][0] + b0, 0.f);
            lo.y = fmaxf(acc[mt][nt][1] + b0, 0.f);
            hi.x = fmaxf(acc[mt][nt][2] + b1, 0.f);
            hi.y = fmaxf(acc[mt][nt][3] + b1, 0.f);
            *(float2*)&g_rpnfeat[ocl * HW + yblk * 256 + col] = lo;
            *(float2*)&g_rpnfeat[(ocl + 8) * HW + yblk * 256 + col] = hi;
        }
    }
}

// =====================================================================
// 1x1 heads + decode, 4-way channel split (unchanged, passing)
// =====================================================================
#define HSM_WS    (45*256)
#define HSM_RED   (3*64*46)
#define HSM_SUMS  (64*46)
#define HSM_BYTES ((HSM_WS + HSM_RED + HSM_SUMS) * 4)

__global__ __launch_bounds__(256)
void heads_decode(const float* __restrict__ cls_w, const float* __restrict__ cls_b,
                  const float* __restrict__ bbox_w, const float* __restrict__ bbox_b)
{
    extern __shared__ float hsm[];
    float* ws   = hsm;
    float* red  = hsm + HSM_WS;
    float* sums = red + HSM_RED;

    const int tid = threadIdx.x;
    for (int i = tid; i < 9 * 256; i += 256)  ws[(i >> 8) * 256 + (i & 255)] = cls_w[i];
    for (int i = tid; i < 36 * 256; i += 256) ws[(9 + (i >> 8)) * 256 + (i & 255)] = bbox_w[i];
    __syncthreads();

    const int q  = tid >> 6;
    const int pl = tid & 63;
    const int p  = (blockIdx.x << 6) + pl;

    float acc[45];
#pragma unroll
    for (int j = 0; j < 45; j++) acc[j] = 0.f;

    const float* rf = g_rpnfeat + (q << 6) * HW + p;
    const float* wq = ws + (q << 6);
    for (int cc = 0; cc < 64; cc++) {
        float v = rf[cc * HW];
#pragma unroll
        for (int j = 0; j < 45; j++) acc[j] = fmaf(wq[j * 256 + cc], v, acc[j]);
    }

    if (q) {
        float* r = red + ((q - 1) * 64 + pl) * 46;
#pragma unroll
        for (int j = 0; j < 45; j++) r[j] = acc[j];
    }
    __syncthreads();
    if (q == 0) {
        float* s = sums + pl * 46;
#pragma unroll
        for (int j = 0; j < 45; j++) {
            float tt = acc[j];
            tt += red[(pl) * 46 + j];
            tt += red[(64 + pl) * 46 + j];
            tt += red[(128 + pl) * 46 + j];
            s[j] = tt;
        }
    }
    __syncthreads();

    const float AR[3]  = {0.5f, 1.0f, 2.0f};
    const float SCL[3] = {128.f, 256.f, 512.f};

    for (int t = tid; t < 576; t += 256) {
        int pxl = t / 9;
        int a   = t - pxl * 9;
        const float* s = sums + pxl * 46;
        int pg = (blockIdx.x << 6) + pxl;
        int x = pg & 127;
        int yv = pg >> 7;
        float sx = (float)x * STRIDE;
        float sy = (float)yv * STRIDE;

        int ia = a / 3, is_ = a - ia * 3;
        float hr  = sqrtf(AR[ia]);
        float wr  = __fdiv_rn(1.0f, hr);
        float hsv = __fmul_rn(hr, SCL[is_]);
        float wsv = __fmul_rn(wr, SCL[is_]);
        float bx1 = rintf(__fmul_rn(-wsv, 0.5f));
        float by1 = rintf(__fmul_rn(-hsv, 0.5f));
        float bx2 = rintf(__fmul_rn(wsv, 0.5f));
        float by2 = rintf(__fmul_rn(hsv, 0.5f));
        float ax1 = __fadd_rn(sx, bx1), ay1 = __fadd_rn(sy, by1);
        float ax2 = __fadd_rn(sx, bx2), ay2 = __fadd_rn(sy, by2);
        float aw = __fsub_rn(ax2, ax1), ah = __fsub_rn(ay2, ay1);
        float cx = __fadd_rn(ax1, __fmul_rn(0.5f, aw));
        float cy = __fadd_rn(ay1, __fmul_rn(0.5f, ah));

        float dx = s[9 + a * 4 + 0] + bbox_b[a * 4 + 0];
        float dy = s[9 + a * 4 + 1] + bbox_b[a * 4 + 1];
        float dw = fminf(s[9 + a * 4 + 2] + bbox_b[a * 4 + 2], DWCLIP);
        float dh = fminf(s[9 + a * 4 + 3] + bbox_b[a * 4 + 3], DWCLIP);

        float px = __fadd_rn(__fmul_rn(dx, aw), cx);
        float py = __fadd_rn(__fmul_rn(dy, ah), cy);
        float pw = __fmul_rn((float)exp((double)dw), aw);
        float ph = __fmul_rn((float)exp((double)dh), ah);

        float x1 = __fsub_rn(px, __fmul_rn(0.5f, pw));
        float y1 = __fsub_rn(py, __fmul_rn(0.5f, ph));
        float x2 = __fadd_rn(px, __fmul_rn(0.5f, pw));
        float y2 = __fadd_rn(py, __fmul_rn(0.5f, ph));

        int idx = pg * 9 + a;
        g_boxes[idx * 4 + 0] = x1;
        g_boxes[idx * 4 + 1] = y1;
        g_boxes[idx * 4 + 2] = x2;
        g_boxes[idx * 4 + 3] = y2;

        float cls = s[a] + cls_b[a];
        float sc = (float)(1.0 / (1.0 + exp(-(double)cls)));
        unsigned sb = __float_as_uint(sc);
        g_keys[idx] = ((unsigned long long)sb << 32) | (unsigned)(0xFFFFFFFFu - (unsigned)idx);
    }
}

// =====================================================================
// Two-level radix select (unchanged)
// =====================================================================
__global__ __launch_bounds__(1024)
void hist_top()
{
    __shared__ int h[4096];
    const int tid = threadIdx.x;
    for (int i = tid; i < 4096; i += 1024) h[i] = 0;
    __syncthreads();
    for (int i = blockIdx.x * 1024 + tid; i < NANCH; i += gridDim.x * 1024)
        atomicAdd(&h[(unsigned)(g_keys[i] >> 52)], 1);
    __syncthreads();
    for (int i = tid; i < 4096; i += 1024) {
        int v = h[i];
        if (v) atomicAdd(&g_hist1[i], v);
    }
}

__global__ __launch_bounds__(1024)
void hist_in_bin()
{
    __shared__ int h[4096];
    const int tid = threadIdx.x;
    const unsigned b1 = (unsigned)g_B1;
    for (int i = tid; i < 4096; i += 1024) h[i] = 0;
    __syncthreads();
    for (int i = blockIdx.x * 1024 + tid; i < NANCH; i += gridDim.x * 1024) {
        unsigned long long key = g_keys[i];
        if ((unsigned)(key >> 52) == b1)
            atomicAdd(&h[(unsigned)((key >> 40) & 0xFFFull)], 1);
    }
    __syncthreads();
    for (int i = tid; i < 4096; i += 1024) {
        int v = h[i];
        if (v) atomicAdd(&g_hist2[i], v);
    }
}

__global__ __launch_bounds__(1024)
void scan_select(int phase)
{
    __shared__ int s[1024];
    const int t = threadIdx.x;
    const int* h = phase ? g_hist2 : g_hist1;
    const int base = phase ? g_cntgt : 0;
    int c[4];
    c[0] = h[4 * t]; c[1] = h[4 * t + 1]; c[2] = h[4 * t + 2]; c[3] = h[4 * t + 3];
    int v = c[0] + c[1] + c[2] + c[3];
    s[t] = v;
    __syncthreads();
    for (int off = 1; off < 1024; off <<= 1) {
        int add = (t + off < 1024) ? s[t + off] : 0;
        __syncthreads();
        v += add;
        s[t] = v;
        __syncthreads();
    }
    int suff = s[t];
    int above = (t < 1023) ? s[t + 1] : 0;
    if (base + above < TOPK && base + suff >= TOPK) {
        int cum = base + above;
#pragma unroll
        for (int b = 3; b >= 0; b--) {
            int hb = c[b];
            if (cum + hb >= TOPK) {
                if (phase == 0) { g_B1 = 4 * t + b; g_cntgt = cum; }
                else            { g_T = ((unsigned)g_B1 << 12) | (unsigned)(4 * t + b); }
                break;
            }
            cum += hb;
        }
    }
    if (phase) {
        if (t == 0) g_selcnt = 0;
        for (int i = t; i < NSEL; i += 1024) g_sel[i] = 0ull;
    }
}

__global__ __launch_bounds__(1024)
void compact_sel()
{
    const unsigned T = g_T;
    for (int i = blockIdx.x * 1024 + threadIdx.x; i < NANCH; i += gridDim.x * 1024) {
        unsigned long long key = g_keys[i];
        if ((unsigned)(key >> 40) >= T) {
            int p = atomicAdd(&g_selcnt, 1);
            if (p < NSEL) g_sel[p] = key;
        }
    }
}

// =====================================================================
// Sort the <=8192 candidates descending (unchanged)
// =====================================================================
__global__ __launch_bounds__(1024)
void sel_local()
{
    __shared__ unsigned long long s[2048];
    const int base = blockIdx.x << 11;
    s[threadIdx.x]        = g_sel[base + threadIdx.x];
    s[threadIdx.x + 1024] = g_sel[base + threadIdx.x + 1024];
    __syncthreads();
    for (int k = 2; k <= 2048; k <<= 1) {
        for (int j = k >> 1; j > 0; j >>= 1) {
            int t = threadIdx.x;
            int i = (t << 1) - (t & (j - 1));
            bool desc = (((base + i) & k) == 0);
            unsigned long long a = s[i], b = s[i + j];
            if ((a < b) == desc) { s[i] = b; s[i + j] = a; }
            __syncthreads();
        }
    }
    g_sel[base + threadIdx.x]        = s[threadIdx.x];
    g_sel[base + threadIdx.x + 1024] = s[threadIdx.x + 1024];
}

__global__ __launch_bounds__(1024)
void sel_merge()
{
    extern __shared__ unsigned long long s[];
    const int tid = threadIdx.x;
#pragma unroll
    for (int q = 0; q < 8; q++) s[tid + (q << 10)] = g_sel[tid + (q << 10)];
    __syncthreads();
    for (int k = 4096; k <= NSEL; k <<= 1) {
        for (int j = k >> 1; j > 0; j >>= 1) {
#pragma unroll
            for (int q = 0; q < 4; q++) {
                int t = tid + (q << 10);
                int i = (t << 1) - (t & (j - 1));
                bool desc = ((i & k) == 0);
                unsigned long long a = s[i], b = s[i + j];
                if ((a < b) == desc) { s[i] = b; s[i + j] = a; }
            }
            __syncthreads();
        }
    }
#pragma unroll
    for (int q = 0; q < 8; q++) g_sel[tid + (q << 10)] = s[tid + (q << 10)];
}

// =====================================================================
// NMS with removed-bitmap + register boxes (unchanged, passing)
// =====================================================================
__global__ __launch_bounds__(1024)
void nms_out(float* __restrict__ out)
{
    extern __shared__ float sm[];
    float* sx1 = sm;
    float* sy1 = sm + TOPK;
    float* sx2 = sm + 2 * TOPK;
    float* sy2 = sm + 3 * TOPK;
    float* sar = sm + 4 * TOPK;
    unsigned* sbits = (unsigned*)(sm + 5 * TOPK);
    __shared__ int keepList[POSTK];

    const int tid = threadIdx.x;
    if (tid < NBITW) sbits[tid] = 0u;
    __syncthreads();

    float rx1[6], ry1[6], rx2[6], ry2[6], rar[6];
    unsigned remloc = 0;
#pragma unroll
    for (int k = 0; k < 6; k++) {
        int j = tid + (k << 10);
        if (j < TOPK) {
            unsigned long long key = g_sel[j];
            unsigned idx = 0xFFFFFFFFu - (unsigned)(key & 0xFFFFFFFFull);
            float b0 = g_boxes[idx * 4 + 0];
            float b1 = g_boxes[idx * 4 + 1];
            float b2 = g_boxes[idx * 4 + 2];
            float b3 = g_boxes[idx * 4 + 3];
            float x1 = fminf(fmaxf(b0, 0.f), IMSZ);
            float y1 = fminf(fmaxf(b1, 0.f), IMSZ);
            float x2 = fminf(fmaxf(b2, 0.f), IMSZ);
            float y2 = fminf(fmaxf(b3, 0.f), IMSZ);
            float wv = __fsub_rn(x2, x1);
            float hv = __fsub_rn(y2, y1);
            sx1[j] = x1; sy1[j] = y1; sx2[j] = x2; sy2[j] = y2;
            float ar = __fmul_rn(wv, hv);
            sar[j] = ar;
            rx1[k] = x1; ry1[k] = y1; rx2[k] = x2; ry2[k] = y2; rar[k] = ar;
            if (!(wv >= MINSZ && hv >= MINSZ)) {
                remloc |= 1u << k;
                atomicOr(&sbits[j >> 5], 1u << (j & 31));
            }
        } else {
            remloc |= 1u << k;
        }
    }
    if (tid == 0) atomicOr(&sbits[NBITW - 1], 0xFFFF0000u);
    __syncthreads();

    int count = 0;
    int i = 0;
    for (;;) {
        while (i < TOPK) {
            unsigned w = (~sbits[i >> 5]) & (0xFFFFFFFFu << (i & 31));
            if (w) { i = (i & ~31) + (__ffs(w) - 1); break; }
            i = (i & ~31) + 32;
        }
        if (i >= TOPK) break;
        if (tid == 0) keepList[count] = i;
        float bx1 = sx1[i], by1 = sy1[i], bx2 = sx2[i], by2 = sy2[i], ba = sar[i];
#pragma unroll
        for (int k = 0; k < 6; k++) {
            int j = tid + (k << 10);
            if (j > i && !((remloc >> k) & 1u)) {
                float xx1 = fmaxf(bx1, rx1[k]);
                float yy1 = fmaxf(by1, ry1[k]);
                float xx2 = fminf(bx2, rx2[k]);
                float yy2 = fminf(by2, ry2[k]);
                float iw = fmaxf(__fsub_rn(xx2, xx1), 0.f);
                float ih = fmaxf(__fsub_rn(yy2, yy1), 0.f);
                float inter = __fmul_rn(iw, ih);
                float denom = __fsub_rn(__fadd_rn(ba, rar[k]), inter);
                if (__fdiv_rn(inter, denom) > NMSTHR) {
                    remloc |= 1u << k;
                    atomicOr(&sbits[j >> 5], 1u << (j & 31));
                }
            }
        }
        count++;
        i++;
        if (count >= POSTK) break;
        __syncthreads();
    }
    __syncthreads();

    for (int t = tid; t < POSTK; t += blockDim.x) {
        if (t < count) {
            int ii = keepList[t];
            unsigned long long key = g_sel[ii];
            out[t * 5 + 0] = sx1[ii];
            out[t * 5 + 1] = sy1[ii];
            out[t * 5 + 2] = sx2[ii];
            out[t * 5 + 3] = sy2[ii];
            out[t * 5 + 4] = __uint_as_float((unsigned)(key >> 32));
        } else {
            out[t * 5 + 0] = 0.f; out[t * 5 + 1] = 0.f; out[t * 5 + 2] = 0.f;
            out[t * 5 + 3] = 0.f; out[t * 5 + 4] = 0.f;
        }
    }
}

// ---------------- launch ----------------
extern "C" void kernel_launch(void* const* d_in, const int* in_sizes, int n_in,
                              void* d_out, int out_size)
{
    (void)in_sizes; (void)n_in; (void)out_size;
    const float* feat   = (const float*)d_in[1];
    const float* conv_w = (const float*)d_in[2];
    const float* conv_b = (const float*)d_in[3];
    const float* cls_w  = (const float*)d_in[4];
    const float* cls_b  = (const float*)d_in[5];
    const float* bbox_w = (const float*)d_in[6];
    const float* bbox_b = (const float*)d_in[7];
    float* out = (float*)d_out;

    prep_w<<<256, 256>>>(conv_w);
    prep_feat<<<PADH, 256>>>(feat);

    cudaFuncSetAttribute(conv_mma, cudaFuncAttributeMaxDynamicSharedMemorySize, DYNSM);
    conv_mma<<<dim3(64, 2), 512, DYNSM>>>(conv_b);

    cudaFuncSetAttribute(heads_decode, cudaFuncAttributeMaxDynamicSharedMemorySize, HSM_BYTES);
    heads_decode<<<256, 256, HSM_BYTES>>>(cls_w, cls_b, bbox_w, bbox_b);

    hist_top<<<144, 1024>>>();
    scan_select<<<1, 1024>>>(0);
    hist_in_bin<<<144, 1024>>>();
    scan_select<<<1, 1024>>>(1);
    compact_sel<<<144, 1024>>>();
    sel_local<<<4, 1024>>>();
    cudaFuncSetAttribute(sel_merge, cudaFuncAttributeMaxDynamicSharedMemorySize, NSEL * 8);
    sel_merge<<<1, 1024, NSEL * 8>>>();

    const int nms_smem = TOPK * 5 * (int)sizeof(float) + NBITW * (int)sizeof(unsigned);
    cudaFuncSetAttribute(nms_out, cudaFuncAttributeMaxDynamicSharedMemorySize, nms_smem);
    nms_out<<<1, 1024, nms_smem>>>(out);
}

// round 8
// speedup vs baseline: 1.4004x; 1.2814x over previous
#include <cuda_runtime.h>
#include <cuda_fp16.h>
#include <cstdint>
#include <math.h>

// ---------------- problem constants ----------------
#define HW      16384           // 128*128 spatial
#define CH      256
#define NANCH   147456          // HW*9
#define TOPK    6000
#define POSTK   300
#define STRIDE  8.0f
#define IMSZ    1024.0f
#define DWCLIP  4.135166556742356f
#define NMSTHR  0.7f
#define MINSZ   16.0f

#define PADW    132
#define PADH    130
#define PADHW   (PADW*PADH)     // 17160

#define NSEL    8192
#define NBITW   188             // ceil(6016/32)

// conv tiling: CTA = 128 oc x 256 px, BK=64 ic, 36 stages (9 taps x 4 chunks)
#define NSTAGE  36
#define RSB     144             // smem row stride bytes (64 fp16 = 128B data + 16 pad)
#define RSW     36              // row stride in words
#define A_SEC   18432           // 128 rows * 144B
#define B_SEC   36864           // 256 rows * 144B
#define BUFB    (2*A_SEC + 2*B_SEC)   // 110592 B per stage buffer
#define DYNSM   (2*BUFB)              // 221184

// ---------------- scratch (device globals; no allocations allowed) ----------------
__device__ float g_rpnfeat[CH * HW];                          // conv out [oc][p]
__device__ __align__(256) __half g_tb[2 * PADHW * 256];       // feat splits [s][y][x][ic]
__device__ __align__(256) __half g_wa[2 * 9 * 256 * 256];     // w splits [s][tap][oc][ic]
__device__ float g_boxes[NANCH * 4];
__device__ unsigned long long g_keys[NANCH];
__device__ unsigned long long g_sel[NSEL];
__device__ int g_hist1[4096];
__device__ int g_hist2[4096];
__device__ int g_B1;
__device__ int g_cntgt;
__device__ unsigned g_T;
__device__ int g_selcnt;

// ---------------- helpers ----------------
__device__ __forceinline__ uint32_t smem_u32(const void* p) {
    uint32_t a;
    asm("{ .reg .u64 t; cvta.to.shared.u64 t, %1; cvt.u32.u64 %0, t; }" : "=r"(a) : "l"(p));
    return a;
}
#define CP_ASYNC16(dst, src) \
    asm volatile("cp.async.cg.shared.global [%0], [%1], 16;" :: "r"(dst), "l"(src))
#define CP_COMMIT()  asm volatile("cp.async.commit_group;" ::: "memory")
#define CP_WAIT0()   asm volatile("cp.async.wait_group 0;" ::: "memory")

#define MMA16816(d, a, b) \
    asm volatile("mma.sync.aligned.m16n8k16.row.col.f32.f16.f16.f32 " \
        "{%0,%1,%2,%3}, {%4,%5,%6,%7}, {%8,%9}, {%0,%1,%2,%3};" \
        : "+f"((d)[0]), "+f"((d)[1]), "+f"((d)[2]), "+f"((d)[3]) \
        : "r"((a)[0]), "r"((a)[1]), "r"((a)[2]), "r"((a)[3]), "r"((b)[0]), "r"((b)[1]))

// =====================================================================
// prep: split weights into 2 fp16 planes [split][tap][oc][ic]; zero hists
// =====================================================================
__global__ __launch_bounds__(256)
void prep_w(const float* __restrict__ w)
{
    int idx = blockIdx.x * 256 + threadIdx.x;     // 65536: oc*256+ic
    if (idx < 4096) g_hist1[idx] = 0;
    else if (idx < 8192) g_hist2[idx - 4096] = 0;
    int oc = idx >> 8, ic = idx & 255;
#pragma unroll
    for (int tap = 0; tap < 9; tap++) {
        float x = w[oc * 2304 + ic * 9 + tap];
        __half h0 = __float2half_rn(x);
        __half h1 = __float2half_rn(x - __half2float(h0));
        int base = (tap * 256 + oc) * 256 + ic;
        g_wa[base] = h0;
        g_wa[9 * 65536 + base] = h1;
    }
}

// prep: tiled transpose feat [ic][p] -> [split][padpos][ic], fp16 2-split
__global__ __launch_bounds__(1024)
void prep_feat(const float* __restrict__ feat)
{
    __shared__ float sm[32][33];
    const int px0 = blockIdx.x << 5;          // 0..16352, within one image row
    const int ic0 = blockIdx.y << 5;
    const int tx = threadIdx.x, ty = threadIdx.y;
    sm[ty][tx] = feat[(ic0 + ty) * HW + px0 + tx];
    __syncthreads();
    float v = sm[tx][ty];                     // channel ic0+tx, pixel px0+ty
    __half h0 = __float2half_rn(v);
    __half h1 = __float2half_rn(v - __half2float(h0));
    const int p = px0 + ty;
    const int yv = p >> 7, xv = p & 127;
    const int padpos = (yv + 1) * PADW + xv + 1;
    const int waddr = padpos * 256 + ic0 + tx;
    g_tb[waddr] = h0;
    g_tb[PADHW * 256 + waddr] = h1;
}

// prep: zero halo positions of g_tb (776 positions x 256 ic x 2 splits)
__global__ __launch_bounds__(256)
void prep_halo()
{
    int hid = blockIdx.x;     // 0..775
    int yp, xp;
    if (hid < 132)            { yp = 0;   xp = hid; }
    else if (hid < 264)       { yp = 129; xp = hid - 132; }
    else {
        int r = hid - 264;
        yp = 1 + (r >> 2);
        int c = r & 3;
        xp = (c == 0) ? 0 : 128 + c;      // 0,129,130,131
    }
    int base = (yp * PADW + xp) * 256 + threadIdx.x;
    g_tb[base] = __float2half_rn(0.f);
    g_tb[PADHW * 256 + base] = __float2half_rn(0.f);
}

// =====================================================================
// conv 3x3 256->256 + bias + ReLU via mma.sync fp16 2-split (3 products)
// =====================================================================
__device__ __forceinline__ void issue_stage(uint32_t sbase, int s, int tid, int yblk, int oc0)
{
    const int tap = s >> 2;
    const int icb = (s & 3) << 7;        // ic-chunk * 64 * 2 bytes
    const int ky = tap / 3, kx = tap - ky * 3;
#pragma unroll
    for (int i = 0; i < 12; i++) {
        int cid = tid + (i << 9);        // 6144 chunks of 16B
        int row = cid >> 3, c = cid & 7;
        const char* src;
        uint32_t dst;
        if (row < 256) {
            int sp = row >> 7, r = row & 127;
            src = (const char*)g_wa + ((sp * 9 + tap) * 256 + oc0 + r) * 512 + icb;
            dst = sbase + sp * A_SEC + r * RSB;
        } else {
            int rowb = row - 256;
            int sp = rowb >> 8, p = rowb & 255;
            int yy = (yblk << 1) + (p >> 7) + ky;
            int xx = (p & 127) + kx;
            src = (const char*)g_tb + (sp * PADHW + yy * PADW + xx) * 512 + icb;
            dst = sbase + 2 * A_SEC + sp * B_SEC + p * RSB;
        }
        CP_ASYNC16(dst + c * 16, src + c * 16);
    }
    CP_COMMIT();
}

__global__ void __launch_bounds__(512, 1) conv_mma(const float* __restrict__ bias)
{
    extern __shared__ char dsm[];
    const uint32_t smem_base = smem_u32(dsm);
    const int tid = threadIdx.x;
    const int yblk = blockIdx.x;          // 0..63 (pair of image rows)
    const int oc0 = blockIdx.y << 7;
    const int wid = tid >> 5, lane = tid & 31;
    const int wm = wid & 3, wn = wid >> 2;
    const int g = lane >> 2, t = lane & 3;

    float acc[2][8][4];
#pragma unroll
    for (int mt = 0; mt < 2; mt++)
#pragma unroll
        for (int nt = 0; nt < 8; nt++)
#pragma unroll
            for (int c = 0; c < 4; c++) acc[mt][nt][c] = 0.f;

    issue_stage(smem_base, 0, tid, yblk, oc0);
    CP_WAIT0();
    __syncthreads();

    for (int s = 0; s < NSTAGE; s++) {
        if (s + 1 < NSTAGE)
            issue_stage(smem_base + ((s + 1) & 1) * BUFB, s + 1, tid, yblk, oc0);

        const uint32_t* smw = (const uint32_t*)(dsm + (s & 1) * BUFB);
#pragma unroll
        for (int k16 = 0; k16 < 4; k16++) {
            const int ko = k16 * 8 + t;
            uint32_t af[2][2][4];
#pragma unroll
            for (int sp = 0; sp < 2; sp++)
#pragma unroll
                for (int mt = 0; mt < 2; mt++) {
                    int row = wm * 32 + mt * 16 + g;
                    int base = sp * (A_SEC / 4) + row * RSW + ko;
                    af[sp][mt][0] = smw[base];
                    af[sp][mt][1] = smw[base + 8 * RSW];
                    af[sp][mt][2] = smw[base + 4];
                    af[sp][mt][3] = smw[base + 8 * RSW + 4];
                }
#pragma unroll
            for (int sb = 0; sb < 2; sb++) {
                uint32_t bf_[8][2];
#pragma unroll
                for (int nt = 0; nt < 8; nt++) {
                    int n = wn * 64 + nt * 8 + g;
                    int base = 2 * (A_SEC / 4) + sb * (B_SEC / 4) + n * RSW + ko;
                    bf_[nt][0] = smw[base];
                    bf_[nt][1] = smw[base + 4];
                }
                const int nsa = (sb == 0) ? 2 : 1;   // products: 00, 10, 01
#pragma unroll
                for (int sa = 0; sa < 2; sa++) {
                    if (sa < nsa) {
#pragma unroll
                        for (int mt = 0; mt < 2; mt++)
#pragma unroll
                            for (int nt = 0; nt < 8; nt++)
                                MMA16816(acc[mt][nt], af[sa][mt], bf_[nt]);
                    }
                }
            }
        }

        if (s + 1 < NSTAGE) {
            CP_WAIT0();
            __syncthreads();
        }
    }

    // epilogue: bias + relu, direct STG (float2)
#pragma unroll
    for (int mt = 0; mt < 2; mt++) {
        int ocl = oc0 + wm * 32 + mt * 16 + g;
        float b0 = bias[ocl];
        float b1 = bias[ocl + 8];
#pragma unroll
        for (int nt = 0; nt < 8; nt++) {
            int col = wn * 64 + nt * 8 + 2 * t;
            float2 lo, hi;
            lo.x = fmaxf(acc[mt][nt][0] + b0, 0.f);
            lo.y = fmaxf(acc[mt][nt][1] + b0, 0.f);
            hi.x = fmaxf(acc[mt][nt][2] + b1, 0.f);
            hi.y = fmaxf(acc[mt][nt][3] + b1, 0.f);
            *(float2*)&g_rpnfeat[ocl * HW + yblk * 256 + col] = lo;
            *(float2*)&g_rpnfeat[(ocl + 8) * HW + yblk * 256 + col] = hi;
        }
    }
}

// =====================================================================
// 1x1 heads + decode: 16 px x 16 channel-groups per block, grid 1024.
// red[16][16][45] ALIASES ws[45][256] (both 11520 floats).
// =====================================================================
#define HSM_FLOATS (11520 + 720)
#define HSM_BYTES  (HSM_FLOATS * 4)

__global__ __launch_bounds__(256)
void heads_decode(const float* __restrict__ cls_w, const float* __restrict__ cls_b,
                  const float* __restrict__ bbox_w, const float* __restrict__ bbox_b)
{
    extern __shared__ float hsm[];
    float* ws   = hsm;                 // ws[j*256+c], j<45
    float* red  = hsm;                 // red[(q*16+pl)*45 + j]  (aliases ws)
    float* sums = hsm + 11520;         // sums[pl*45 + j]

    const int tid = threadIdx.x;
    for (int i = tid; i < 9 * 256; i += 256)  ws[(i >> 8) * 256 + (i & 255)] = cls_w[i];
    for (int i = tid; i < 36 * 256; i += 256) ws[(9 + (i >> 8)) * 256 + (i & 255)] = bbox_w[i];
    __syncthreads();

    const int pl = tid & 15;
    const int q  = tid >> 4;
    const int p  = (blockIdx.x << 4) + pl;

    float acc[45];
#pragma unroll
    for (int j = 0; j < 45; j++) acc[j] = 0.f;

    const float* rf = g_rpnfeat + (q << 4) * HW + p;
    const float* wq = ws + (q << 4);
#pragma unroll
    for (int cc = 0; cc < 16; cc++) {
        float v = rf[cc * HW];
#pragma unroll
        for (int j = 0; j < 45; j++) acc[j] = fmaf(wq[j * 256 + cc], v, acc[j]);
    }
    __syncthreads();     // all ws reads complete before aliasing as red

    {
        float* r = red + (q * 16 + pl) * 45;
#pragma unroll
        for (int j = 0; j < 45; j++) r[j] = acc[j];
    }
    __syncthreads();

    for (int task = tid; task < 720; task += 256) {
        int pl2 = task / 45, j = task - pl2 * 45;
        float s = 0.f;
#pragma unroll
        for (int q2 = 0; q2 < 16; q2++)
            s += red[(q2 * 16 + pl2) * 45 + j];
        sums[pl2 * 45 + j] = s;
    }
    __syncthreads();

    const float AR[3]  = {0.5f, 1.0f, 2.0f};
    const float SCL[3] = {128.f, 256.f, 512.f};

    if (tid < 144) {
        int pxl = tid / 9;
        int a   = tid - pxl * 9;
        const float* s = sums + pxl * 45;
        int pg = (blockIdx.x << 4) + pxl;
        int x = pg & 127;
        int yv = pg >> 7;
        float sx = (float)x * STRIDE;
        float sy = (float)yv * STRIDE;

        int ia = a / 3, is_ = a - ia * 3;
        float hr  = sqrtf(AR[ia]);
        float wr  = __fdiv_rn(1.0f, hr);
        float hsv = __fmul_rn(hr, SCL[is_]);
        float wsv = __fmul_rn(wr, SCL[is_]);
        float bx1 = rintf(__fmul_rn(-wsv, 0.5f));
        float by1 = rintf(__fmul_rn(-hsv, 0.5f));
        float bx2 = rintf(__fmul_rn(wsv, 0.5f));
        float by2 = rintf(__fmul_rn(hsv, 0.5f));
        float ax1 = __fadd_rn(sx, bx1), ay1 = __fadd_rn(sy, by1);
        float ax2 = __fadd_rn(sx, bx2), ay2 = __fadd_rn(sy, by2);
        float aw = __fsub_rn(ax2, ax1), ah = __fsub_rn(ay2, ay1);
        float cx = __fadd_rn(ax1, __fmul_rn(0.5f, aw));
        float cy = __fadd_rn(ay1, __fmul_rn(0.5f, ah));

        float dx = s[9 + a * 4 + 0] + bbox_b[a * 4 + 0];
        float dy = s[9 + a * 4 + 1] + bbox_b[a * 4 + 1];
        float dw = fminf(s[9 + a * 4 + 2] + bbox_b[a * 4 + 2], DWCLIP);
        float dh = fminf(s[9 + a * 4 + 3] + bbox_b[a * 4 + 3], DWCLIP);

        float px = __fadd_rn(__fmul_rn(dx, aw), cx);
        float py = __fadd_rn(__fmul_rn(dy, ah), cy);
        float pw = __fmul_rn((float)exp((double)dw), aw);
        float ph = __fmul_rn((float)exp((double)dh), ah);

        float x1 = __fsub_rn(px, __fmul_rn(0.5f, pw));
        float y1 = __fsub_rn(py, __fmul_rn(0.5f, ph));
        float x2 = __fadd_rn(px, __fmul_rn(0.5f, pw));
        float y2 = __fadd_rn(py, __fmul_rn(0.5f, ph));

        int idx = pg * 9 + a;
        g_boxes[idx * 4 + 0] = x1;
        g_boxes[idx * 4 + 1] = y1;
        g_boxes[idx * 4 + 2] = x2;
        g_boxes[idx * 4 + 3] = y2;

        float cls = s[a] + cls_b[a];
        float sc = (float)(1.0 / (1.0 + exp(-(double)cls)));
        unsigned sb = __float_as_uint(sc);
        g_keys[idx] = ((unsigned long long)sb << 32) | (unsigned)(0xFFFFFFFFu - (unsigned)idx);
    }
}

// =====================================================================
// Two-level radix select (unchanged)
// =====================================================================
__global__ __launch_bounds__(1024)
void hist_top()
{
    __shared__ int h[4096];
    const int tid = threadIdx.x;
    for (int i = tid; i < 4096; i += 1024) h[i] = 0;
    __syncthreads();
    for (int i = blockIdx.x * 1024 + tid; i < NANCH; i += gridDim.x * 1024)
        atomicAdd(&h[(unsigned)(g_keys[i] >> 52)], 1);
    __syncthreads();
    for (int i = tid; i < 4096; i += 1024) {
        int v = h[i];
        if (v) atomicAdd(&g_hist1[i], v);
    }
}

__global__ __launch_bounds__(1024)
void hist_in_bin()
{
    __shared__ int h[4096];
    const int tid = threadIdx.x;
    const unsigned b1 = (unsigned)g_B1;
    for (int i = tid; i < 4096; i += 1024) h[i] = 0;
    __syncthreads();
    for (int i = blockIdx.x * 1024 + tid; i < NANCH; i += gridDim.x * 1024) {
        unsigned long long key = g_keys[i];
        if ((unsigned)(key >> 52) == b1)
            atomicAdd(&h[(unsigned)((key >> 40) & 0xFFFull)], 1);
    }
    __syncthreads();
    for (int i = tid; i < 4096; i += 1024) {
        int v = h[i];
        if (v) atomicAdd(&g_hist2[i], v);
    }
}

__global__ __launch_bounds__(1024)
void scan_select(int phase)
{
    __shared__ int s[1024];
    const int t = threadIdx.x;
    const int* h = phase ? g_hist2 : g_hist1;
    const int base = phase ? g_cntgt : 0;
    int c[4];
    c[0] = h[4 * t]; c[1] = h[4 * t + 1]; c[2] = h[4 * t + 2]; c[3] = h[4 * t + 3];
    int v = c[0] + c[1] + c[2] + c[3];
    s[t] = v;
    __syncthreads();
    for (int off = 1; off < 1024; off <<= 1) {
        int add = (t + off < 1024) ? s[t + off] : 0;
        __syncthreads();
        v += add;
        s[t] = v;
        __syncthreads();
    }
    int suff = s[t];
    int above = (t < 1023) ? s[t + 1] : 0;
    if (base + above < TOPK && base + suff >= TOPK) {
        int cum = base + above;
#pragma unroll
        for (int b = 3; b >= 0; b--) {
            int hb = c[b];
            if (cum + hb >= TOPK) {
                if (phase == 0) { g_B1 = 4 * t + b; g_cntgt = cum; }
                else            { g_T = ((unsigned)g_B1 << 12) | (unsigned)(4 * t + b); }
                break;
            }
            cum += hb;
        }
    }
    if (phase) {
        if (t == 0) g_selcnt = 0;
        for (int i = t; i < NSEL; i += 1024) g_sel[i] = 0ull;
    }
}

__global__ __launch_bounds__(1024)
void compact_sel()
{
    const unsigned T = g_T;
    for (int i = blockIdx.x * 1024 + threadIdx.x; i < NANCH; i += gridDim.x * 1024) {
        unsigned long long key = g_keys[i];
        if ((unsigned)(key >> 40) >= T) {
            int p = atomicAdd(&g_selcnt, 1);
            if (p < NSEL) g_sel[p] = key;
        }
    }
}

// =====================================================================
// Sort the <=8192 candidates descending (unchanged)
// =====================================================================
__global__ __launch_bounds__(1024)
void sel_local()
{
    __shared__ unsigned long long s[2048];
    const int base = blockIdx.x << 11;
    s[threadIdx.x]        = g_sel[base + threadIdx.x];
    s[threadIdx.x + 1024] = g_sel[base + threadIdx.x + 1024];
    __syncthreads();
    for (int k = 2; k <= 2048; k <<= 1) {
        for (int j = k >> 1; j > 0; j >>= 1) {
            int t = threadIdx.x;
            int i = (t << 1) - (t & (j - 1));
            bool desc = (((base + i) & k) == 0);
            unsigned long long a = s[i], b = s[i + j];
            if ((a < b) == desc) { s[i] = b; s[i + j] = a; }
            __syncthreads();
        }
    }
    g_sel[base + threadIdx.x]        = s[threadIdx.x];
    g_sel[base + threadIdx.x + 1024] = s[threadIdx.x + 1024];
}

__global__ __launch_bounds__(1024)
void sel_merge()
{
    extern __shared__ unsigned long long s[];
    const int tid = threadIdx.x;
#pragma unroll
    for (int q = 0; q < 8; q++) s[tid + (q << 10)] = g_sel[tid + (q << 10)];
    __syncthreads();
    for (int k = 4096; k <= NSEL; k <<= 1) {
        for (int j = k >> 1; j > 0; j >>= 1) {
#pragma unroll
            for (int q = 0; q < 4; q++) {
                int t = tid + (q << 10);
                int i = (t << 1) - (t & (j - 1));
                bool desc = ((i & k) == 0);
                unsigned long long a = s[i], b = s[i + j];
                if ((a < b) == desc) { s[i] = b; s[i + j] = a; }
            }
            __syncthreads();
        }
    }
#pragma unroll
    for (int q = 0; q < 8; q++) g_sel[tid + (q << 10)] = s[tid + (q << 10)];
}

// =====================================================================
// NMS with removed-bitmap + register boxes (unchanged, passing)
// =====================================================================
__global__ __launch_bounds__(1024)
void nms_out(float* __restrict__ out)
{
    extern __shared__ float sm[];
    float* sx1 = sm;
    float* sy1 = sm + TOPK;
    float* sx2 = sm + 2 * TOPK;
    float* sy2 = sm + 3 * TOPK;
    float* sar = sm + 4 * TOPK;
    unsigned* sbits = (unsigned*)(sm + 5 * TOPK);
    __shared__ int keepList[POSTK];

    const int tid = threadIdx.x;
    if (tid < NBITW) sbits[tid] = 0u;
    __syncthreads();

    float rx1[6], ry1[6], rx2[6], ry2[6], rar[6];
    unsigned remloc = 0;
#pragma unroll
    for (int k = 0; k < 6; k++) {
        int j = tid + (k << 10);
        if (j < TOPK) {
            unsigned long long key = g_sel[j];
            unsigned idx = 0xFFFFFFFFu - (unsigned)(key & 0xFFFFFFFFull);
            float b0 = g_boxes[idx * 4 + 0];
            float b1 = g_boxes[idx * 4 + 1];
            float b2 = g_boxes[idx * 4 + 2];
            float b3 = g_boxes[idx * 4 + 3];
            float x1 = fminf(fmaxf(b0, 0.f), IMSZ);
            float y1 = fminf(fmaxf(b1, 0.f), IMSZ);
            float x2 = fminf(fmaxf(b2, 0.f), IMSZ);
            float y2 = fminf(fmaxf(b3, 0.f), IMSZ);
            float wv = __fsub_rn(x2, x1);
            float hv = __fsub_rn(y2, y1);
            sx1[j] = x1; sy1[j] = y1; sx2[j] = x2; sy2[j] = y2;
            float ar = __fmul_rn(wv, hv);
            sar[j] = ar;
            rx1[k] = x1; ry1[k] = y1; rx2[k] = x2; ry2[k] = y2; rar[k] = ar;
            if (!(wv >= MINSZ && hv >= MINSZ)) {
                remloc |= 1u << k;
                atomicOr(&sbits[j >> 5], 1u << (j & 31));
            }
        } else {
            remloc |= 1u << k;
        }
    }
    if (tid == 0) atomicOr(&sbits[NBITW - 1], 0xFFFF0000u);
    __syncthreads();

    int count = 0;
    int i = 0;
    for (;;) {
        while (i < TOPK) {
            unsigned w = (~sbits[i >> 5]) & (0xFFFFFFFFu << (i & 31));
            if (w) { i = (i & ~31) + (__ffs(w) - 1); break; }
            i = (i & ~31) + 32;
        }
        if (i >= TOPK) break;
        if (tid == 0) keepList[count] = i;
        float bx1 = sx1[i], by1 = sy1[i], bx2 = sx2[i], by2 = sy2[i], ba = sar[i];
#pragma unroll
        for (int k = 0; k < 6; k++) {
            int j = tid + (k << 10);
            if (j > i && !((remloc >> k) & 1u)) {
                float xx1 = fmaxf(bx1, rx1[k]);
                float yy1 = fmaxf(by1, ry1[k]);
                float xx2 = fminf(bx2, rx2[k]);
                float yy2 = fminf(by2, ry2[k]);
                float iw = fmaxf(__fsub_rn(xx2, xx1), 0.f);
                float ih = fmaxf(__fsub_rn(yy2, yy1), 0.f);
                float inter = __fmul_rn(iw, ih);
                float denom = __fsub_rn(__fadd_rn(ba, rar[k]), inter);
                if (__fdiv_rn(inter, denom) > NMSTHR) {
                    remloc |= 1u << k;
                    atomicOr(&sbits[j >> 5], 1u << (j & 31));
                }
            }
        }
        count++;
        i++;
        if (count >= POSTK) break;
        __syncthreads();
    }
    __syncthreads();

    for (int t = tid; t < POSTK; t += blockDim.x) {
        if (t < count) {
            int ii = keepList[t];
            unsigned long long key = g_sel[ii];
            out[t * 5 + 0] = sx1[ii];
            out[t * 5 + 1] = sy1[ii];
            out[t * 5 + 2] = sx2[ii];
            out[t * 5 + 3] = sy2[ii];
            out[t * 5 + 4] = __uint_as_float((unsigned)(key >> 32));
        } else {
            out[t * 5 + 0] = 0.f; out[t * 5 + 1] = 0.f; out[t * 5 + 2] = 0.f;
            out[t * 5 + 3] = 0.f; out[t * 5 + 4] = 0.f;
        }
    }
}

// ---------------- launch ----------------
extern "C" void kernel_launch(void* const* d_in, const int* in_sizes, int n_in,
                              void* d_out, int out_size)
{
    (void)in_sizes; (void)n_in; (void)out_size;
    const float* feat   = (const float*)d_in[1];
    const float* conv_w = (const float*)d_in[2];
    const float* conv_b = (const float*)d_in[3];
    const float* cls_w  = (const float*)d_in[4];
    const float* cls_b  = (const float*)d_in[5];
    const float* bbox_w = (const float*)d_in[6];
    const float* bbox_b = (const float*)d_in[7];
    float* out = (float*)d_out;

    prep_w<<<256, 256>>>(conv_w);
    prep_feat<<<dim3(512, 8), dim3(32, 32)>>>(feat);
    prep_halo<<<776, 256>>>();

    cudaFuncSetAttribute(conv_mma, cudaFuncAttributeMaxDynamicSharedMemorySize, DYNSM);
    conv_mma<<<dim3(64, 2), 512, DYNSM>>>(conv_b);

    cudaFuncSetAttribute(heads_decode, cudaFuncAttributeMaxDynamicSharedMemorySize, HSM_BYTES);
    heads_decode<<<1024, 256, HSM_BYTES>>>(cls_w, cls_b, bbox_w, bbox_b);

    hist_top<<<144, 1024>>>();
    scan_select<<<1, 1024>>>(0);
    hist_in_bin<<<144, 1024>>>();
    scan_select<<<1, 1024>>>(1);
    compact_sel<<<144, 1024>>>();
    sel_local<<<4, 1024>>>();
    cudaFuncSetAttribute(sel_merge, cudaFuncAttributeMaxDynamicSharedMemorySize, NSEL * 8);
    sel_merge<<<1, 1024, NSEL * 8>>>();

    const int nms_smem = TOPK * 5 * (int)sizeof(float) + NBITW * (int)sizeof(unsigned);
    cudaFuncSetAttribute(nms_out, cudaFuncAttributeMaxDynamicSharedMemorySize, nms_smem);
    nms_out<<<1, 1024, nms_smem>>>(out);
}